// round 1
// baseline (speedup 1.0000x reference)
#include <cuda_runtime.h>

// out[b,i,:] = sum_j exp(q_i . k_j) * v_j   (B=4, S=4096, D=64, fp32)
//
// SIMT fp32 baseline: 128x128 tiles, 256 threads, 8x8 / 8x4 micro-tiles.
// Q,K staged transposed in smem ([d][row]) for vectorized LDS.128 reads;
// P = exp(S) staged through smem row-major.

#define TQ 128
#define TK 128
#define DD 64
#define NTHREADS 256
#define S_LEN 4096
#define B_SZ 4

// smem strides (floats); all multiples of 4 to keep float4 alignment
#define QK_LD 132   // Qst/Kst: [64 d][128 rows + 4 pad]
#define V_LD  68    // Vs: [128 keys][64 d + 4 pad]
#define P_LD  132   // Ps: [128 q-rows][128 keys + 4 pad]

#define QST_OFF 0
#define KST_OFF (QST_OFF + DD * QK_LD)       // 8448
#define VS_OFF  (KST_OFF + DD * QK_LD)       // 16896
#define PS_OFF  (VS_OFF + TK * V_LD)         // 25600
#define SMEM_FLOATS (PS_OFF + TQ * P_LD)     // 42496 floats = 169984 B

__global__ void __launch_bounds__(NTHREADS, 1)
fa_exp_kernel(const float* __restrict__ q, const float* __restrict__ k,
              const float* __restrict__ v, float* __restrict__ out)
{
    extern __shared__ float sm[];
    float* Qst = sm + QST_OFF;
    float* Kst = sm + KST_OFF;
    float* Vs  = sm + VS_OFF;
    float* Ps  = sm + PS_OFF;

    const int tid = threadIdx.x;
    const int tx  = tid & 15;   // 0..15
    const int ty  = tid >> 4;   // 0..15
    const int b   = blockIdx.y;
    const int q0  = blockIdx.x * TQ;

    const float* Qg = q + ((size_t)b * S_LEN + q0) * DD;
    const float* Kg = k + (size_t)b * S_LEN * DD;
    const float* Vg = v + (size_t)b * S_LEN * DD;
    float*       Og = out + ((size_t)b * S_LEN + q0) * DD;

    // ---- load Q tile once, transposed: Qst[d][row] ----
    {
        const int r0 = tid >> 4;          // 0..15
        const int d  = (tid & 15) << 2;   // 0,4,...,60
        #pragma unroll
        for (int it = 0; it < 8; ++it) {
            int r = r0 + it * 16;         // 0..127
            float4 t = *(const float4*)&Qg[r * DD + d];
            Qst[(d + 0) * QK_LD + r] = t.x;
            Qst[(d + 1) * QK_LD + r] = t.y;
            Qst[(d + 2) * QK_LD + r] = t.z;
            Qst[(d + 3) * QK_LD + r] = t.w;
        }
    }

    float acc2[8][4];
    #pragma unroll
    for (int i = 0; i < 8; ++i)
        #pragma unroll
        for (int j = 0; j < 4; ++j) acc2[i][j] = 0.0f;

    const int ntiles = S_LEN / TK;
    for (int kt = 0; kt < ntiles; ++kt) {
        __syncthreads();   // previous GEMM2 done reading Vs/Ps before overwrite

        // ---- load K tile (transposed) and V tile (row-major) ----
        {
            const int r0 = tid >> 4;
            const int d  = (tid & 15) << 2;
            const float* Kt = Kg + (size_t)kt * TK * DD;
            const float* Vt = Vg + (size_t)kt * TK * DD;
            #pragma unroll
            for (int it = 0; it < 8; ++it) {
                int r = r0 + it * 16;
                float4 t = *(const float4*)&Kt[r * DD + d];
                Kst[(d + 0) * QK_LD + r] = t.x;
                Kst[(d + 1) * QK_LD + r] = t.y;
                Kst[(d + 2) * QK_LD + r] = t.z;
                Kst[(d + 3) * QK_LD + r] = t.w;
                float4 tv = *(const float4*)&Vt[r * DD + d];
                *(float4*)&Vs[r * V_LD + d] = tv;
            }
        }
        __syncthreads();

        // ---- GEMM1: S = Q @ K^T  (8x8 micro-tile per thread) ----
        float acc1[8][8];
        #pragma unroll
        for (int i = 0; i < 8; ++i)
            #pragma unroll
            for (int j = 0; j < 8; ++j) acc1[i][j] = 0.0f;

        #pragma unroll 4
        for (int d = 0; d < DD; ++d) {
            float4 qa = *(const float4*)&Qst[d * QK_LD + 8 * ty];
            float4 qb = *(const float4*)&Qst[d * QK_LD + 8 * ty + 4];
            float4 ka = *(const float4*)&Kst[d * QK_LD + 8 * tx];
            float4 kb = *(const float4*)&Kst[d * QK_LD + 8 * tx + 4];
            float qv[8] = {qa.x, qa.y, qa.z, qa.w, qb.x, qb.y, qb.z, qb.w};
            float kv[8] = {ka.x, ka.y, ka.z, ka.w, kb.x, kb.y, kb.z, kb.w};
            #pragma unroll
            for (int i = 0; i < 8; ++i)
                #pragma unroll
                for (int j = 0; j < 8; ++j)
                    acc1[i][j] = fmaf(qv[i], kv[j], acc1[i][j]);
        }

        // ---- exp and stage P to smem (row-major [q][key]) ----
        #pragma unroll
        for (int i = 0; i < 8; ++i) {
            float4 e0, e1;
            e0.x = __expf(acc1[i][0]); e0.y = __expf(acc1[i][1]);
            e0.z = __expf(acc1[i][2]); e0.w = __expf(acc1[i][3]);
            e1.x = __expf(acc1[i][4]); e1.y = __expf(acc1[i][5]);
            e1.z = __expf(acc1[i][6]); e1.w = __expf(acc1[i][7]);
            *(float4*)&Ps[(8 * ty + i) * P_LD + 8 * tx]     = e0;
            *(float4*)&Ps[(8 * ty + i) * P_LD + 8 * tx + 4] = e1;
        }
        __syncthreads();

        // ---- GEMM2: O += P @ V  (8x4 micro-tile, 4 keys per step) ----
        #pragma unroll 2
        for (int key = 0; key < TK; key += 4) {
            float4 v0 = *(const float4*)&Vs[(key + 0) * V_LD + 4 * tx];
            float4 v1 = *(const float4*)&Vs[(key + 1) * V_LD + 4 * tx];
            float4 v2 = *(const float4*)&Vs[(key + 2) * V_LD + 4 * tx];
            float4 v3 = *(const float4*)&Vs[(key + 3) * V_LD + 4 * tx];
            #pragma unroll
            for (int i = 0; i < 8; ++i) {
                float4 p = *(const float4*)&Ps[(8 * ty + i) * P_LD + key];
                acc2[i][0] = fmaf(p.x, v0.x, acc2[i][0]);
                acc2[i][1] = fmaf(p.x, v0.y, acc2[i][1]);
                acc2[i][2] = fmaf(p.x, v0.z, acc2[i][2]);
                acc2[i][3] = fmaf(p.x, v0.w, acc2[i][3]);
                acc2[i][0] = fmaf(p.y, v1.x, acc2[i][0]);
                acc2[i][1] = fmaf(p.y, v1.y, acc2[i][1]);
                acc2[i][2] = fmaf(p.y, v1.z, acc2[i][2]);
                acc2[i][3] = fmaf(p.y, v1.w, acc2[i][3]);
                acc2[i][0] = fmaf(p.z, v2.x, acc2[i][0]);
                acc2[i][1] = fmaf(p.z, v2.y, acc2[i][1]);
                acc2[i][2] = fmaf(p.z, v2.z, acc2[i][2]);
                acc2[i][3] = fmaf(p.z, v2.w, acc2[i][3]);
                acc2[i][0] = fmaf(p.w, v3.x, acc2[i][0]);
                acc2[i][1] = fmaf(p.w, v3.y, acc2[i][1]);
                acc2[i][2] = fmaf(p.w, v3.z, acc2[i][2]);
                acc2[i][3] = fmaf(p.w, v3.w, acc2[i][3]);
            }
        }
    }

    // ---- epilogue: O[8ty+i][4tx + j] ----
    #pragma unroll
    for (int i = 0; i < 8; ++i) {
        float4 o = make_float4(acc2[i][0], acc2[i][1], acc2[i][2], acc2[i][3]);
        *(float4*)&Og[(8 * ty + i) * DD + 4 * tx] = o;
    }
}

extern "C" void kernel_launch(void* const* d_in, const int* in_sizes, int n_in,
                              void* d_out, int out_size)
{
    const float* q = (const float*)d_in[0];
    const float* k = (const float*)d_in[1];
    const float* v = (const float*)d_in[2];
    float* out = (float*)d_out;

    (void)in_sizes; (void)n_in; (void)out_size;

    const int smem_bytes = SMEM_FLOATS * (int)sizeof(float);
    cudaFuncSetAttribute(fa_exp_kernel,
                         cudaFuncAttributeMaxDynamicSharedMemorySize, smem_bytes);

    dim3 grid(S_LEN / TQ, B_SZ);   // 32 x 4 = 128 blocks
    fa_exp_kernel<<<grid, NTHREADS, smem_bytes>>>(q, k, v, out);
}

// round 3
// speedup vs baseline: 2.2302x; 2.2302x over previous
#include <cuda_runtime.h>
#include <cuda_bf16.h>
#include <cstdint>

// out[b,i,:] = sum_j exp(q_i . k_j) * v_j   (B=4, S=4096, D=64, fp32)
// mma.sync (HMMA) bf16 split-precision: x = x_hi + x_lo (bf16),
// GEMM = hi*hi + hi*lo + lo*hi (lo*lo dropped, ~2^-18 rel).
// NOTE: tcgen05/TMA are unavailable (harness PTX target is compute_103,
// not 103a) — mma.sync + ldmatrix are the portable tensor path.

#define S_LEN 4096
#define B_SZ  4
#define DD    64
#define TQ    128
#define TK    128
#define NTH   256
#define NTILES (S_LEN / TK)

// row pitches (bytes): 144 = 64 bf16 + 8 pad  -> conflict-free ldmatrix
//                      272 = 128 bf16 + 8 pad
#define QK_PITCH 144
#define P_PITCH  272

#define SM_QHI 0
#define SM_QLO (SM_QHI + 128 * QK_PITCH)
#define SM_KHI (SM_QLO + 128 * QK_PITCH)
#define SM_KLO (SM_KHI + 128 * QK_PITCH)
#define SM_VHI (SM_KLO + 128 * QK_PITCH)
#define SM_VLO (SM_VHI + 128 * QK_PITCH)
#define SM_PHI (SM_VLO + 128 * QK_PITCH)
#define SM_PLO (SM_PHI + 128 * P_PITCH)
#define SM_TOTAL (SM_PLO + 128 * P_PITCH)   // 180224 B

#define QKBUF (128 * QK_PITCH)   // 18432
#define PBUF  (128 * P_PITCH)    // 34816

// ---------------- PTX helpers ----------------
__device__ __forceinline__ uint32_t smem_u32(const void* p) {
    uint32_t a;
    asm("{ .reg .u64 t; cvta.to.shared.u64 t, %1; cvt.u32.u64 %0, t; }" : "=r"(a) : "l"(p));
    return a;
}

#define LDMX4(r, a) \
    asm volatile("ldmatrix.sync.aligned.m8n8.x4.shared.b16 {%0,%1,%2,%3}, [%4];" \
        : "=r"((r)[0]), "=r"((r)[1]), "=r"((r)[2]), "=r"((r)[3]) : "r"(a))
#define LDMX2(r, a) \
    asm volatile("ldmatrix.sync.aligned.m8n8.x2.shared.b16 {%0,%1}, [%2];" \
        : "=r"((r)[0]), "=r"((r)[1]) : "r"(a))
#define LDMX2T(r, a) \
    asm volatile("ldmatrix.sync.aligned.m8n8.x2.trans.shared.b16 {%0,%1}, [%2];" \
        : "=r"((r)[0]), "=r"((r)[1]) : "r"(a))
#define MMA(c, av, bv) \
    asm volatile("mma.sync.aligned.m16n8k16.row.col.f32.bf16.bf16.f32 " \
        "{%0,%1,%2,%3}, {%4,%5,%6,%7}, {%8,%9}, {%0,%1,%2,%3};" \
        : "+f"((c)[0]), "+f"((c)[1]), "+f"((c)[2]), "+f"((c)[3]) \
        : "r"((av)[0]), "r"((av)[1]), "r"((av)[2]), "r"((av)[3]), \
          "r"((bv)[0]), "r"((bv)[1]))

__device__ __forceinline__ void split_pack(float x, float y, uint32_t& hi, uint32_t& lo) {
    __nv_bfloat16 xh = __float2bfloat16(x), yh = __float2bfloat16(y);
    float xr = x - __bfloat162float(xh);
    float yr = y - __bfloat162float(yh);
    __nv_bfloat16 xl = __float2bfloat16(xr), yl = __float2bfloat16(yr);
    hi = ((uint32_t)__bfloat16_as_ushort(yh) << 16) | (uint32_t)__bfloat16_as_ushort(xh);
    lo = ((uint32_t)__bfloat16_as_ushort(yl) << 16) | (uint32_t)__bfloat16_as_ushort(xl);
}

// load+split one 128x64 fp32 tile into hi/lo bf16 smem buffers (pitch 144B)
__device__ __forceinline__ void stage_tile(const float* __restrict__ g,
                                           char* smhi, char* smlo, int tid) {
    #pragma unroll
    for (int i = 0; i < 8; ++i) {
        int f = tid + i * NTH;             // 0..2047 float4 units
        int row = f >> 4, d0 = (f & 15) << 2;
        float4 t = *(const float4*)&g[(size_t)row * DD + d0];
        uint32_t h0, l0, h1, l1;
        split_pack(t.x, t.y, h0, l0);
        split_pack(t.z, t.w, h1, l1);
        int off = row * QK_PITCH + d0 * 2;
        *(uint2*)(smhi + off) = make_uint2(h0, h1);
        *(uint2*)(smlo + off) = make_uint2(l0, l1);
    }
}

__global__ void __launch_bounds__(NTH, 1)
fa_mma_kernel(const float* __restrict__ q, const float* __restrict__ k,
              const float* __restrict__ v, float* __restrict__ out)
{
    extern __shared__ char smem[];
    const uint32_t sb = smem_u32(smem);
    const int tid  = threadIdx.x;
    const int wid  = tid >> 5;
    const int lane = tid & 31;
    const int b  = blockIdx.y;
    const int q0 = blockIdx.x * TQ;

    const int wrow  = (wid & 3) * 32;   // S/O row base of this warp
    const int wcolS = (wid >> 2) * 64;  // S col base (GEMM1)
    const int wcolO = (wid >> 2) * 32;  // O col base (GEMM2)

    const float* Qg = q + ((size_t)b * S_LEN + q0) * DD;
    const float* Kg = k + (size_t)b * S_LEN * DD;
    const float* Vg = v + (size_t)b * S_LEN * DD;
    float*       Og = out + ((size_t)b * S_LEN + q0) * DD;

    // ---- stage Q once ----
    stage_tile(Qg, smem + SM_QHI, smem + SM_QLO, tid);

    // precomputed per-lane smem addresses
    const uint32_t aQ = sb + SM_QHI + (uint32_t)((wrow + (lane & 15)) * QK_PITCH + (lane >> 4) * 16);
    const uint32_t bK = sb + SM_KHI + (uint32_t)((wcolS + (lane & 7)) * QK_PITCH + ((lane >> 3) & 1) * 16);
    const uint32_t aP = sb + SM_PHI + (uint32_t)((wrow + (lane & 15)) * P_PITCH + (lane >> 4) * 16);
    const uint32_t bV = sb + SM_VHI + (uint32_t)((lane & 15) * QK_PITCH + wcolO * 2);
    const uint32_t pW = sb + SM_PHI + (uint32_t)((wrow + (lane >> 2)) * P_PITCH + (wcolS + (lane & 3) * 2) * 2);

    float acc2[2][4][4];   // O accum: [mi][ni][frag], persistent
    #pragma unroll
    for (int mi = 0; mi < 2; ++mi)
        #pragma unroll
        for (int ni = 0; ni < 4; ++ni)
            #pragma unroll
            for (int e = 0; e < 4; ++e) acc2[mi][ni][e] = 0.0f;

    for (int t = 0; t < NTILES; ++t) {
        __syncthreads();   // prev GEMM2 done reading V/P before overwrite

        stage_tile(Kg + (size_t)(t * TK) * DD, smem + SM_KHI, smem + SM_KLO, tid);
        stage_tile(Vg + (size_t)(t * TK) * DD, smem + SM_VHI, smem + SM_VLO, tid);
        __syncthreads();

        // ---- GEMM1: S(128x128) = Q @ K^T, split 3-term ----
        float acc1[2][8][4];
        #pragma unroll
        for (int mi = 0; mi < 2; ++mi)
            #pragma unroll
            for (int ni = 0; ni < 8; ++ni)
                #pragma unroll
                for (int e = 0; e < 4; ++e) acc1[mi][ni][e] = 0.0f;

        #pragma unroll
        for (int ks = 0; ks < 4; ++ks) {       // k = 64 in steps of 16
            uint32_t ahi[2][4], alo[2][4];
            #pragma unroll
            for (int mi = 0; mi < 2; ++mi) {
                uint32_t a = aQ + (uint32_t)(mi * 16 * QK_PITCH + ks * 32);
                LDMX4(ahi[mi], a);
                LDMX4(alo[mi], a + QKBUF);
            }
            #pragma unroll
            for (int ni = 0; ni < 8; ++ni) {
                uint32_t bb = bK + (uint32_t)(ni * 8 * QK_PITCH + ks * 32);
                uint32_t bhi[2], blo[2];
                LDMX2(bhi, bb);
                LDMX2(blo, bb + QKBUF);
                #pragma unroll
                for (int mi = 0; mi < 2; ++mi) {
                    MMA(acc1[mi][ni], ahi[mi], bhi);
                    MMA(acc1[mi][ni], ahi[mi], blo);
                    MMA(acc1[mi][ni], alo[mi], bhi);
                }
            }
        }

        // ---- P = exp(S): split hi/lo, stage to smem ----
        #pragma unroll
        for (int mi = 0; mi < 2; ++mi) {
            #pragma unroll
            for (int ni = 0; ni < 8; ++ni) {
                float e0 = __expf(acc1[mi][ni][0]);
                float e1 = __expf(acc1[mi][ni][1]);
                float e2 = __expf(acc1[mi][ni][2]);
                float e3 = __expf(acc1[mi][ni][3]);
                uint32_t h01, l01, h23, l23;
                split_pack(e0, e1, h01, l01);
                split_pack(e2, e3, h23, l23);
                uint32_t w0 = pW + (uint32_t)(mi * 16 * P_PITCH + ni * 16);
                uint32_t w1 = w0 + 8 * P_PITCH;
                asm volatile("st.shared.b32 [%0], %1;" :: "r"(w0), "r"(h01));
                asm volatile("st.shared.b32 [%0], %1;" :: "r"(w0 + PBUF), "r"(l01));
                asm volatile("st.shared.b32 [%0], %1;" :: "r"(w1), "r"(h23));
                asm volatile("st.shared.b32 [%0], %1;" :: "r"(w1 + PBUF), "r"(l23));
            }
        }
        __syncthreads();

        // ---- GEMM2: O(128x64) += P @ V, split 3-term ----
        #pragma unroll
        for (int ks = 0; ks < 8; ++ks) {       // keys = 128 in steps of 16
            uint32_t ahi[2][4], alo[2][4];
            #pragma unroll
            for (int mi = 0; mi < 2; ++mi) {
                uint32_t a = aP + (uint32_t)(mi * 16 * P_PITCH + ks * 32);
                LDMX4(ahi[mi], a);
                LDMX4(alo[mi], a + PBUF);
            }
            #pragma unroll
            for (int ni = 0; ni < 4; ++ni) {
                uint32_t bb = bV + (uint32_t)(ks * 16 * QK_PITCH + ni * 16);
                uint32_t bhi[2], blo[2];
                LDMX2T(bhi, bb);
                LDMX2T(blo, bb + QKBUF);
                #pragma unroll
                for (int mi = 0; mi < 2; ++mi) {
                    MMA(acc2[mi][ni], ahi[mi], bhi);
                    MMA(acc2[mi][ni], ahi[mi], blo);
                    MMA(acc2[mi][ni], alo[mi], bhi);
                }
            }
        }
    }

    // ---- epilogue: store O ----
    #pragma unroll
    for (int mi = 0; mi < 2; ++mi) {
        #pragma unroll
        for (int ni = 0; ni < 4; ++ni) {
            int r = wrow + mi * 16 + (lane >> 2);
            int c = wcolO + ni * 8 + (lane & 3) * 2;
            *(float2*)&Og[(size_t)r * DD + c] =
                make_float2(acc2[mi][ni][0], acc2[mi][ni][1]);
            *(float2*)&Og[(size_t)(r + 8) * DD + c] =
                make_float2(acc2[mi][ni][2], acc2[mi][ni][3]);
        }
    }
}

extern "C" void kernel_launch(void* const* d_in, const int* in_sizes, int n_in,
                              void* d_out, int out_size)
{
    const float* q = (const float*)d_in[0];
    const float* k = (const float*)d_in[1];
    const float* v = (const float*)d_in[2];
    float* out = (float*)d_out;
    (void)in_sizes; (void)n_in; (void)out_size;

    cudaFuncSetAttribute(fa_mma_kernel,
                         cudaFuncAttributeMaxDynamicSharedMemorySize, SM_TOTAL);
    dim3 grid(S_LEN / TQ, B_SZ);   // 32 x 4 = 128 CTAs, one wave
    fa_mma_kernel<<<grid, NTH, SM_TOTAL>>>(q, k, v, out);
}